// round 1
// baseline (speedup 1.0000x reference)
#include <cuda_runtime.h>
#include <math.h>

#define BB 4
#define QQ 100
#define CC 3
#define NT 10
#define HWP 65536

// ---- scratch (device globals; no allocations allowed) ----
__device__ unsigned short g_bits[BB * HWP];   // packed target bitmask per (b,h)
__device__ int            g_tsum[BB * NT];    // per-target pixel counts
__device__ float          g_cost[BB * QQ * NT];
__device__ float          g_cmask[BB * QQ * NT];
__device__ int            g_matchq[BB * NT];  // matched query for target (b,n)
__device__ float          g_ssig[BB * NT];
__device__ float          g_inter[BB * NT];

// ---------------------------------------------------------------------------
__global__ void k_zero() {
    int t = threadIdx.x;
    if (t < BB * NT) g_tsum[t] = 0;
}

// Pack binary targets into 16-bit masks + count pixels per target.
__global__ void k_pack(const float* __restrict__ tgt) {
    int idx = blockIdx.x * blockDim.x + threadIdx.x;  // 0 .. B*HW-1
    int b = idx >> 16;
    int h = idx & (HWP - 1);
    int lane = threadIdx.x & 31;
    unsigned bits = 0;
#pragma unroll
    for (int n = 0; n < NT; n++) {
        float v = tgt[((size_t)(b * NT + n)) * HWP + h];
        int on = v > 0.0f;
        bits |= ((unsigned)on) << n;
        unsigned ball = __ballot_sync(0xffffffffu, on);
        if (lane == 0) atomicAdd(&g_tsum[b * NT + n], __popc(ball));
    }
    g_bits[idx] = (unsigned short)bits;
}

// ---------------------------------------------------------------------------
// One block per (b,q). Computes sum softplus(pm) and dot(pm, t[n]) for all n,
// then cost_mask and cost (mask + class).
__global__ void k_cost(const float* __restrict__ pm,
                       const float* __restrict__ logits,
                       const int* __restrict__ labels) {
    int b = blockIdx.x / QQ;
    int q = blockIdx.x % QQ;
    const float4* x4 = (const float4*)(pm + ((size_t)(b * QQ + q)) * HWP);
    const unsigned long long* w8 =
        (const unsigned long long*)(g_bits + (size_t)b * HWP);

    float ssp = 0.0f;
    float d[NT];
#pragma unroll
    for (int n = 0; n < NT; n++) d[n] = 0.0f;

    for (int i = threadIdx.x; i < HWP / 4; i += blockDim.x) {
        float4 xv = x4[i];
        unsigned long long w = w8[i];
        float xs[4] = {xv.x, xv.y, xv.z, xv.w};
#pragma unroll
        for (int p = 0; p < 4; p++) {
            float x = xs[p];
            unsigned bi = ((unsigned)(w >> (16 * p))) & 1023u;
            float a = fabsf(x);
            float e = __expf(-a);
            float sp = fmaxf(x, 0.0f) + __logf(1.0f + e);
            ssp += sp;
#pragma unroll
            for (int n = 0; n < NT; n++)
                if (bi & (1u << n)) d[n] += x;
        }
    }

    // block reduction (11 values)
    __shared__ float red[8][NT + 1];
    int lane = threadIdx.x & 31, wid = threadIdx.x >> 5;
#pragma unroll
    for (int o = 16; o; o >>= 1) {
        ssp += __shfl_down_sync(0xffffffffu, ssp, o);
#pragma unroll
        for (int n = 0; n < NT; n++)
            d[n] += __shfl_down_sync(0xffffffffu, d[n], o);
    }
    if (lane == 0) {
        red[wid][0] = ssp;
#pragma unroll
        for (int n = 0; n < NT; n++) red[wid][n + 1] = d[n];
    }
    __syncthreads();

    if (threadIdx.x == 0) {
        float tssp = 0.0f, td[NT];
#pragma unroll
        for (int n = 0; n < NT; n++) td[n] = 0.0f;
        int nw = blockDim.x >> 5;
        for (int wdx = 0; wdx < nw; wdx++) {
            tssp += red[wdx][0];
#pragma unroll
            for (int n = 0; n < NT; n++) td[n] += red[wdx][n + 1];
        }
        // class cost: -softmax(logits)[label]
        float l0 = logits[(b * QQ + q) * CC + 0];
        float l1 = logits[(b * QQ + q) * CC + 1];
        float l2 = logits[(b * QQ + q) * CC + 2];
        float mx = fmaxf(l0, fmaxf(l1, l2));
        float z = __expf(l0 - mx) + __expf(l1 - mx) + __expf(l2 - mx);
        float lse = mx + __logf(z);
        const float inv_hw = 1.0f / (float)HWP;
#pragma unroll
        for (int n = 0; n < NT; n++) {
            int lab = labels[b * NT + n];
            float ll = logits[(b * QQ + q) * CC + lab];
            float cc = -__expf(ll - lse);
            float cm = (tssp - td[n]) * inv_hw;
            g_cmask[(b * QQ + q) * NT + n] = cm;
            g_cost[(b * QQ + q) * NT + n] = cm + cc;
        }
    }
}

// ---------------------------------------------------------------------------
// Warp-parallel Jonker-Volgenant assignment, one warp per batch.
// Replicates the reference algorithm exactly (transposed cost: N rows, Q cols).
__global__ void k_match() {
    __shared__ double sC[BB][NT][QQ];
    __shared__ double sv[BB][QQ + 1];
    __shared__ double su[BB][NT + 1];
    __shared__ int sp_[BB][QQ + 1];
    __shared__ int sway[BB][QQ + 1];
    __shared__ unsigned char sused[BB][QQ + 1];

    int b = threadIdx.x >> 5;
    int lane = threadIdx.x & 31;

    for (int idx = lane; idx < NT * QQ; idx += 32) {
        int i = idx / QQ, j = idx % QQ;
        sC[b][i][j] = (double)g_cost[(b * QQ + j) * NT + i];
    }
    for (int j = lane; j <= QQ; j += 32) {
        sv[b][j] = 0.0;
        sp_[b][j] = 0;
    }
    if (lane <= NT) su[b][lane] = 0.0;
    __syncwarp();

    for (int i = 1; i <= NT; i++) {
        double mv[4];
#pragma unroll
        for (int k = 0; k < 4; k++) mv[k] = 1e18;
        if (lane == 0) sp_[b][0] = i;
        for (int j = lane; j <= QQ; j += 32) sused[b][j] = 0;
        __syncwarp();

        int j0 = 0;
        while (true) {
            if (lane == 0) sused[b][j0] = 1;
            __syncwarp();
            int i0 = sp_[b][j0];
            double ui0 = su[b][i0];

            double best = 1e18;
            int bj = 0;
#pragma unroll
            for (int k = 0; k < 4; k++) {
                int j = 1 + lane + 32 * k;
                if (j <= QQ && !sused[b][j]) {
                    double cur = sC[b][i0 - 1][j - 1] - ui0 - sv[b][j];
                    if (cur < mv[k]) {
                        mv[k] = cur;
                        sway[b][j] = j0;
                    }
                    if (mv[k] < best || (mv[k] == best && j < bj)) {
                        best = mv[k];
                        bj = j;
                    }
                }
            }
            // warp argmin (tie -> smallest j, matching np.argmin order)
#pragma unroll
            for (int o = 16; o; o >>= 1) {
                double ov = __shfl_down_sync(0xffffffffu, best, o);
                int oj = __shfl_down_sync(0xffffffffu, bj, o);
                if (ov < best || (ov == best && oj != 0 && (bj == 0 || oj < bj))) {
                    best = ov;
                    bj = oj;
                }
            }
            double delta = __shfl_sync(0xffffffffu, best, 0);
            int j1 = __shfl_sync(0xffffffffu, bj, 0);
            __syncwarp();

#pragma unroll
            for (int k = 0; k < 4; k++) {
                int j = 1 + lane + 32 * k;
                if (j <= QQ) {
                    if (sused[b][j]) {
                        su[b][sp_[b][j]] += delta;  // rows distinct -> race-free
                        sv[b][j] -= delta;
                    } else {
                        mv[k] -= delta;
                    }
                }
            }
            if (lane == 0) {
                su[b][sp_[b][0]] += delta;
                sv[b][0] -= delta;
            }
            __syncwarp();
            j0 = j1;
            if (sp_[b][j0] == 0) break;
        }
        if (lane == 0) {
            int jj = j0;
            while (jj) {
                int jn = sway[b][jj];
                sp_[b][jj] = sp_[b][jn];
                jj = jn;
            }
        }
        __syncwarp();
    }

    for (int j = 1 + lane; j <= QQ; j += 32) {
        int pi = sp_[b][j];
        if (pi) g_matchq[b * NT + (pi - 1)] = j - 1;
    }
}

// ---------------------------------------------------------------------------
// Dice sums for matched pairs only: sum sigmoid(pm[q_n]) and sum over t[n]=1.
__global__ void k_dice(const float* __restrict__ pm) {
    int b = blockIdx.x / NT, n = blockIdx.x % NT;
    int q = g_matchq[b * NT + n];
    const float4* x4 = (const float4*)(pm + ((size_t)(b * QQ + q)) * HWP);
    const unsigned long long* w8 =
        (const unsigned long long*)(g_bits + (size_t)b * HWP);
    unsigned long long nbit = 1ull << n;

    float ss = 0.0f, si = 0.0f;
    for (int i = threadIdx.x; i < HWP / 4; i += blockDim.x) {
        float4 xv = x4[i];
        unsigned long long w = w8[i];
        float xs[4] = {xv.x, xv.y, xv.z, xv.w};
#pragma unroll
        for (int p = 0; p < 4; p++) {
            float x = xs[p];
            float a = fabsf(x);
            float e = __expf(-a);
            float r = __fdividef(1.0f, 1.0f + e);
            float s = (x >= 0.0f) ? r : e * r;
            ss += s;
            if ((w >> (16 * p)) & nbit) si += s;
        }
    }
    __shared__ float red[8][2];
    int lane = threadIdx.x & 31, wid = threadIdx.x >> 5;
#pragma unroll
    for (int o = 16; o; o >>= 1) {
        ss += __shfl_down_sync(0xffffffffu, ss, o);
        si += __shfl_down_sync(0xffffffffu, si, o);
    }
    if (lane == 0) {
        red[wid][0] = ss;
        red[wid][1] = si;
    }
    __syncthreads();
    if (threadIdx.x == 0) {
        float tss = 0.0f, tsi = 0.0f;
        int nw = blockDim.x >> 5;
        for (int wdx = 0; wdx < nw; wdx++) {
            tss += red[wdx][0];
            tsi += red[wdx][1];
        }
        g_ssig[b * NT + n] = tss;
        g_inter[b * NT + n] = tsi;
    }
}

// ---------------------------------------------------------------------------
__global__ void k_final(const float* __restrict__ logits,
                        const int* __restrict__ labels,
                        float* __restrict__ out) {
    __shared__ float sce[BB * NT], sdi[BB * NT], sbc[BB * NT];
    int t = threadIdx.x;
    if (t < BB * NT) {
        int b = t / NT, n = t % NT;
        int q = g_matchq[t];
        float l0 = logits[(b * QQ + q) * CC + 0];
        float l1 = logits[(b * QQ + q) * CC + 1];
        float l2 = logits[(b * QQ + q) * CC + 2];
        float mx = fmaxf(l0, fmaxf(l1, l2));
        float lse = mx + logf(expf(l0 - mx) + expf(l1 - mx) + expf(l2 - mx));
        int lab = labels[t];
        float ll = (lab == 0) ? l0 : ((lab == 1) ? l1 : l2);
        sce[t] = lse - ll;  // -log_softmax[lab]
        float inter = g_inter[t], ssig = g_ssig[t];
        float ts = (float)g_tsum[t];
        sdi[t] = (2.0f * inter + 1.0f) / (ssig + ts + 1.0f);
        sbc[t] = g_cmask[(b * QQ + q) * NT + n];  // matched BCE == cost_mask
    }
    __syncthreads();
    if (t == 0) {
        float tot = 0.0f, cem = 0.0f, dim = 0.0f;
        for (int b = 0; b < BB; b++) {
            float ce = 0.0f, di = 0.0f, bc = 0.0f;
            for (int n = 0; n < NT; n++) {
                ce += sce[b * NT + n];
                di += sdi[b * NT + n];
                bc += sbc[b * NT + n];
            }
            ce *= (1.0f / NT);
            bc *= (1.0f / NT);
            float ld = 1.0f - di * (1.0f / NT);
            tot += ce + ld + bc;
            cem += ce;
            dim += ld;
        }
        out[0] = tot * (1.0f / BB);
        out[1] = cem * (1.0f / BB);
        out[2] = dim * (1.0f / BB);
    }
}

// ---------------------------------------------------------------------------
extern "C" void kernel_launch(void* const* d_in, const int* in_sizes, int n_in,
                              void* d_out, int out_size) {
    const float* pred_logits = (const float*)d_in[0];
    const float* pred_masks = (const float*)d_in[1];
    const int* tgt_labels = (const int*)d_in[2];
    const float* tgt_masks = (const float*)d_in[3];
    float* out = (float*)d_out;

    k_zero<<<1, 64>>>();
    k_pack<<<(BB * HWP) / 256, 256>>>(tgt_masks);
    k_cost<<<BB * QQ, 256>>>(pred_masks, pred_logits, tgt_labels);
    k_match<<<1, BB * 32>>>();
    k_dice<<<BB * NT, 256>>>(pred_masks);
    k_final<<<1, 64>>>(pred_logits, tgt_labels, out);
}

// round 3
// speedup vs baseline: 1.2232x; 1.2232x over previous
#include <cuda_runtime.h>
#include <math.h>

#define BB 4
#define QQ 100
#define CC 3
#define NT 10
#define HWP 65536
#define DSPLIT 8

// ---- scratch (device globals; no allocations allowed) ----
__device__ unsigned short g_bits[BB * HWP];   // packed target bitmask per (b,h)
__device__ int            g_tsum[BB * NT];    // per-target pixel counts
__device__ float          g_cost[BB * QQ * NT];
__device__ float          g_cmask[BB * QQ * NT];
__device__ int            g_matchq[BB * NT];  // matched query for target (b,n)
__device__ float          g_ssig[BB * NT];
__device__ float          g_inter[BB * NT];

// ---------------------------------------------------------------------------
__global__ void k_zero() {
    int t = threadIdx.x;
    if (t < BB * NT) {
        g_tsum[t] = 0;
        g_ssig[t] = 0.0f;
        g_inter[t] = 0.0f;
    }
}

// Pack binary targets into 16-bit masks + count pixels per target.
__global__ void k_pack(const float* __restrict__ tgt) {
    int idx = blockIdx.x * blockDim.x + threadIdx.x;  // 0 .. B*HW-1
    int b = idx >> 16;
    int h = idx & (HWP - 1);
    int lane = threadIdx.x & 31;
    unsigned bits = 0;
#pragma unroll
    for (int n = 0; n < NT; n++) {
        float v = tgt[((size_t)(b * NT + n)) * HWP + h];
        int on = v > 0.0f;
        bits |= ((unsigned)on) << n;
        unsigned ball = __ballot_sync(0xffffffffu, on);
        if (lane == 0) atomicAdd(&g_tsum[b * NT + n], __popc(ball));
    }
    g_bits[idx] = (unsigned short)bits;
}

// ---------------------------------------------------------------------------
// One block per (b,q). Computes sum softplus(pm) and dot(pm, t[n]) for all n,
// then cost_mask and cost (mask + class).
__global__ void k_cost(const float* __restrict__ pm,
                       const float* __restrict__ logits,
                       const int* __restrict__ labels) {
    int b = blockIdx.x / QQ;
    int q = blockIdx.x % QQ;
    const float4* x4 = (const float4*)(pm + ((size_t)(b * QQ + q)) * HWP);
    const unsigned long long* w8 =
        (const unsigned long long*)(g_bits + (size_t)b * HWP);

    float ssp = 0.0f;
    float d[NT];
#pragma unroll
    for (int n = 0; n < NT; n++) d[n] = 0.0f;

    for (int i = threadIdx.x; i < HWP / 4; i += blockDim.x) {
        float4 xv = x4[i];
        unsigned long long w = w8[i];
        float xs[4] = {xv.x, xv.y, xv.z, xv.w};
#pragma unroll
        for (int p = 0; p < 4; p++) {
            float x = xs[p];
            unsigned bi = ((unsigned)(w >> (16 * p))) & 1023u;
            float a = fabsf(x);
            float e = __expf(-a);
            float sp = fmaxf(x, 0.0f) + __logf(1.0f + e);
            ssp += sp;
#pragma unroll
            for (int n = 0; n < NT; n++)
                if (bi & (1u << n)) d[n] += x;
        }
    }

    // block reduction (11 values)
    __shared__ float red[8][NT + 1];
    int lane = threadIdx.x & 31, wid = threadIdx.x >> 5;
#pragma unroll
    for (int o = 16; o; o >>= 1) {
        ssp += __shfl_down_sync(0xffffffffu, ssp, o);
#pragma unroll
        for (int n = 0; n < NT; n++)
            d[n] += __shfl_down_sync(0xffffffffu, d[n], o);
    }
    if (lane == 0) {
        red[wid][0] = ssp;
#pragma unroll
        for (int n = 0; n < NT; n++) red[wid][n + 1] = d[n];
    }
    __syncthreads();

    if (threadIdx.x == 0) {
        float tssp = 0.0f, td[NT];
#pragma unroll
        for (int n = 0; n < NT; n++) td[n] = 0.0f;
        int nw = blockDim.x >> 5;
        for (int wdx = 0; wdx < nw; wdx++) {
            tssp += red[wdx][0];
#pragma unroll
            for (int n = 0; n < NT; n++) td[n] += red[wdx][n + 1];
        }
        // class cost: -softmax(logits)[label]
        float l0 = logits[(b * QQ + q) * CC + 0];
        float l1 = logits[(b * QQ + q) * CC + 1];
        float l2 = logits[(b * QQ + q) * CC + 2];
        float mx = fmaxf(l0, fmaxf(l1, l2));
        float z = __expf(l0 - mx) + __expf(l1 - mx) + __expf(l2 - mx);
        float lse = mx + __logf(z);
        const float inv_hw = 1.0f / (float)HWP;
#pragma unroll
        for (int n = 0; n < NT; n++) {
            int lab = labels[b * NT + n];
            float ll = logits[(b * QQ + q) * CC + lab];
            float cc = -__expf(ll - lse);
            float cm = (tssp - td[n]) * inv_hw;
            g_cmask[(b * QQ + q) * NT + n] = cm;
            g_cost[(b * QQ + q) * NT + n] = cm + cc;
        }
    }
}

// ---------------------------------------------------------------------------
// Warp-parallel Jonker-Volgenant assignment, one warp per batch.
// fp32, register-resident. Column j (1-indexed) owned by lane (j-1)&31,
// slot (j-1)>>5. Only u[] lives in shared memory.
__global__ void k_match() {
    __shared__ float su[BB][NT + 1];
    const unsigned FULL = 0xffffffffu;
    int b = threadIdx.x >> 5;
    int lane = threadIdx.x & 31;

    float C[4][NT];
    float v[4], mv[4];
    int way[4], p[4], used[4], valid[4];

#pragma unroll
    for (int k = 0; k < 4; k++) {
        int j = 1 + lane + 32 * k;
        valid[k] = (j <= QQ);
        v[k] = 0.0f;
        p[k] = 0;
        way[k] = 0;
        if (valid[k]) {
#pragma unroll
            for (int i = 0; i < NT; i++)
                C[k][i] = g_cost[(b * QQ + (j - 1)) * NT + i];
        }
    }
    if (lane <= NT) su[b][lane] = 0.0f;
    __syncwarp();

    for (int i = 1; i <= NT; i++) {
#pragma unroll
        for (int k = 0; k < 4; k++) {
            mv[k] = 1e30f;
            used[k] = valid[k] ? 0 : 1;
        }
        int p0 = i;  // p[0]
        int j0 = 0;

        while (true) {
            // mark j0 used, fetch i0 = p[j0]
            int i0;
            if (j0 == 0) {
                i0 = p0;
            } else {
                int owner = (j0 - 1) & 31;
                int slot = (j0 - 1) >> 5;
                if (lane == owner) used[slot] = 1;
                int pj = (slot == 0) ? p[0] : (slot == 1) ? p[1]
                         : (slot == 2) ? p[2] : p[3];
                i0 = __shfl_sync(FULL, pj, owner);
            }
            float ui0 = su[b][i0];

            // update minv/way over unused, track per-lane best
            float best = 1e30f;
            int bj = 1 << 20;
#pragma unroll
            for (int k = 0; k < 4; k++) {
                int j = 1 + lane + 32 * k;
                if (!used[k]) {
                    float cur = C[k][i0 - 1] - ui0 - v[k];
                    if (cur < mv[k]) {
                        mv[k] = cur;
                        way[k] = j0;
                    }
                    if (mv[k] < best) {  // k ascending => j ascending; strict
                        best = mv[k];
                        bj = j;
                    }
                }
            }
            // warp argmin, tie -> smallest j (matches np.argmin)
#pragma unroll
            for (int o = 16; o; o >>= 1) {
                float ov = __shfl_down_sync(FULL, best, o);
                int oj = __shfl_down_sync(FULL, bj, o);
                if (ov < best || (ov == best && oj < bj)) {
                    best = ov;
                    bj = oj;
                }
            }
            float delta = __shfl_sync(FULL, best, 0);
            int j1 = __shfl_sync(FULL, bj, 0);

            // dual updates: u[p[used]] += delta, v[used] -= delta, minv -= delta
#pragma unroll
            for (int k = 0; k < 4; k++) {
                if (valid[k]) {
                    if (used[k]) {
                        su[b][p[k]] += delta;  // distinct rows -> race-free
                        v[k] -= delta;
                    } else {
                        mv[k] -= delta;
                    }
                }
            }
            if (lane == 0) su[b][p0] += delta;  // virtual column 0
            __syncwarp();

            j0 = j1;
            // check p[j0] == 0 -> augmenting path found
            int owner = (j0 - 1) & 31;
            int slot = (j0 - 1) >> 5;
            int pj = (slot == 0) ? p[0] : (slot == 1) ? p[1]
                     : (slot == 2) ? p[2] : p[3];
            int pj0 = __shfl_sync(FULL, pj, owner);
            if (pj0 == 0) break;
        }

        // backtrack augmenting path (j0 uniform across warp)
        while (j0) {
            int owner = (j0 - 1) & 31;
            int slot = (j0 - 1) >> 5;
            int wj_l = (slot == 0) ? way[0] : (slot == 1) ? way[1]
                       : (slot == 2) ? way[2] : way[3];
            int wj = __shfl_sync(FULL, wj_l, owner);
            int pv;
            if (wj == 0) {
                pv = p0;
            } else {
                int o2 = (wj - 1) & 31;
                int s2 = (wj - 1) >> 5;
                int pj_l = (s2 == 0) ? p[0] : (s2 == 1) ? p[1]
                           : (s2 == 2) ? p[2] : p[3];
                pv = __shfl_sync(FULL, pj_l, o2);
            }
            if (lane == owner) {
                if (slot == 0) p[0] = pv;
                else if (slot == 1) p[1] = pv;
                else if (slot == 2) p[2] = pv;
                else p[3] = pv;
            }
            j0 = wj;
        }
        __syncwarp();
    }

    // emit matching
#pragma unroll
    for (int k = 0; k < 4; k++) {
        int j = 1 + lane + 32 * k;
        if (valid[k] && p[k]) g_matchq[b * NT + (p[k] - 1)] = j - 1;
    }
}

// ---------------------------------------------------------------------------
// Dice sums for matched pairs: DSPLIT blocks per (b,n), atomic partials.
__global__ void k_dice(const float* __restrict__ pm) {
    int pair = blockIdx.x / DSPLIT;
    int seg = blockIdx.x % DSPLIT;
    int b = pair / NT, n = pair % NT;
    int q = g_matchq[b * NT + n];
    const int CHUNK4 = HWP / 4 / DSPLIT;  // float4 elems per segment
    const float4* x4 = (const float4*)(pm + ((size_t)(b * QQ + q)) * HWP) +
                       seg * CHUNK4;
    const unsigned long long* w8 =
        (const unsigned long long*)(g_bits + (size_t)b * HWP) + seg * CHUNK4;
    unsigned long long nbit = 1ull << n;

    float ss = 0.0f, si = 0.0f;
    for (int i = threadIdx.x; i < CHUNK4; i += blockDim.x) {
        float4 xv = x4[i];
        unsigned long long w = w8[i];
        float xs[4] = {xv.x, xv.y, xv.z, xv.w};
#pragma unroll
        for (int p = 0; p < 4; p++) {
            float x = xs[p];
            float a = fabsf(x);
            float e = __expf(-a);
            float r = __fdividef(1.0f, 1.0f + e);
            float s = (x >= 0.0f) ? r : e * r;
            ss += s;
            if ((w >> (16 * p)) & nbit) si += s;
        }
    }
    __shared__ float red[8][2];
    int lane = threadIdx.x & 31, wid = threadIdx.x >> 5;
#pragma unroll
    for (int o = 16; o; o >>= 1) {
        ss += __shfl_down_sync(0xffffffffu, ss, o);
        si += __shfl_down_sync(0xffffffffu, si, o);
    }
    if (lane == 0) {
        red[wid][0] = ss;
        red[wid][1] = si;
    }
    __syncthreads();
    if (threadIdx.x == 0) {
        float tss = 0.0f, tsi = 0.0f;
        int nw = blockDim.x >> 5;
        for (int wdx = 0; wdx < nw; wdx++) {
            tss += red[wdx][0];
            tsi += red[wdx][1];
        }
        atomicAdd(&g_ssig[b * NT + n], tss);
        atomicAdd(&g_inter[b * NT + n], tsi);
    }
}

// ---------------------------------------------------------------------------
__global__ void k_final(const float* __restrict__ logits,
                        const int* __restrict__ labels,
                        float* __restrict__ out) {
    __shared__ float sce[BB * NT], sdi[BB * NT], sbc[BB * NT];
    int t = threadIdx.x;
    if (t < BB * NT) {
        int b = t / NT, n = t % NT;
        int q = g_matchq[t];
        float l0 = logits[(b * QQ + q) * CC + 0];
        float l1 = logits[(b * QQ + q) * CC + 1];
        float l2 = logits[(b * QQ + q) * CC + 2];
        float mx = fmaxf(l0, fmaxf(l1, l2));
        float lse = mx + logf(expf(l0 - mx) + expf(l1 - mx) + expf(l2 - mx));
        int lab = labels[t];
        float ll = (lab == 0) ? l0 : ((lab == 1) ? l1 : l2);
        sce[t] = lse - ll;  // -log_softmax[lab]
        float inter = g_inter[t], ssig = g_ssig[t];
        float ts = (float)g_tsum[t];
        sdi[t] = (2.0f * inter + 1.0f) / (ssig + ts + 1.0f);
        sbc[t] = g_cmask[(b * QQ + q) * NT + n];  // matched BCE == cost_mask
    }
    __syncthreads();
    if (t == 0) {
        float tot = 0.0f, cem = 0.0f, dim = 0.0f;
        for (int b = 0; b < BB; b++) {
            float ce = 0.0f, di = 0.0f, bc = 0.0f;
            for (int n = 0; n < NT; n++) {
                ce += sce[b * NT + n];
                di += sdi[b * NT + n];
                bc += sbc[b * NT + n];
            }
            ce *= (1.0f / NT);
            bc *= (1.0f / NT);
            float ld = 1.0f - di * (1.0f / NT);
            tot += ce + ld + bc;
            cem += ce;
            dim += ld;
        }
        out[0] = tot * (1.0f / BB);
        out[1] = cem * (1.0f / BB);
        out[2] = dim * (1.0f / BB);
    }
}

// ---------------------------------------------------------------------------
extern "C" void kernel_launch(void* const* d_in, const int* in_sizes, int n_in,
                              void* d_out, int out_size) {
    const float* pred_logits = (const float*)d_in[0];
    const float* pred_masks = (const float*)d_in[1];
    const int* tgt_labels = (const int*)d_in[2];
    const float* tgt_masks = (const float*)d_in[3];
    float* out = (float*)d_out;

    k_zero<<<1, 64>>>();
    k_pack<<<(BB * HWP) / 256, 256>>>(tgt_masks);
    k_cost<<<BB * QQ, 256>>>(pred_masks, pred_logits, tgt_labels);
    k_match<<<1, BB * 32>>>();
    k_dice<<<BB * NT * DSPLIT, 256>>>(pred_masks);
    k_final<<<1, 64>>>(pred_logits, tgt_labels, out);
}